// round 1
// baseline (speedup 1.0000x reference)
#include <cuda_runtime.h>
#include <stdint.h>

// ---------------------------------------------------------------------------
// W4A8 per-group GEMM:  out[m,n] = (sum_k x_i8[m,k] * (q4[n,k]*s2[g,n] + z[g,n]))
//                                   * input_scales[m] * s1_scales[n] + bias[n]
// Key: w = q*s2 + z fits int8 exactly (|w| <= 105), so dequant in the load
// path and run one exact s8*s8->s32 GEMM over the full K via mma.sync (IMMA).
// HBM-bound: qweight = 235 MB of int32-per-nibble that must be streamed once.
// ---------------------------------------------------------------------------

#define M_DIM 64
#define K_DIM 4096
#define N_DIM 14336
#define G_DIM 32
#define GS    128          // group size along K (one K-chunk per group)
#define NT    64           // N columns per CTA -> 224 CTAs
#define BROW  (GS + 16)    // padded smem row (bytes): 144 = 36 words, conflict-free

// int8-packed activations, row-major [M][K] (256 KB scratch; static, alloc-free)
__device__ __align__(16) unsigned int g_x_packed[M_DIM * K_DIM / 4];

// ---- pass 0: pack x int32 -> int8 -------------------------------------------
__global__ void pack_x_kernel(const int* __restrict__ x) {
    int idx = blockIdx.x * blockDim.x + threadIdx.x;   // one 4-byte word
    if (idx >= M_DIM * K_DIM / 4) return;
    const int4 v = reinterpret_cast<const int4*>(x)[idx];
    unsigned a = __byte_perm((unsigned)v.x, (unsigned)v.y, 0x0040);
    unsigned b = __byte_perm((unsigned)v.z, (unsigned)v.w, 0x0040);
    g_x_packed[idx] = __byte_perm(a, b, 0x5410);
}

// ---- main GEMM ---------------------------------------------------------------
__global__ __launch_bounds__(256, 2)
void w4a8_gemm_kernel(const int*   __restrict__ qw,    // [N,K] int32 (values 0..15)
                      const int*   __restrict__ s2s,   // [G,N]
                      const int*   __restrict__ s2z,   // [G,N]
                      const float* __restrict__ isc,   // [M]
                      const float* __restrict__ s1,    // [N]
                      const float* __restrict__ bias,  // [N]
                      float*       __restrict__ out)   // [M,N]
{
    __shared__ __align__(16) unsigned char sA[2][M_DIM * BROW]; // x tile 64x128 i8
    __shared__ __align__(16) unsigned char sB[2][NT * BROW];    // w tile 64x128 i8

    const int tid = threadIdx.x;
    const int n0  = blockIdx.x * NT;

    // B dequant mapping: thread -> (local n row, 32-int segment of K-chunk)
    const int brow = tid >> 2;              // 0..63
    const int bseg = tid & 3;               // 0..3
    const int* qrowp = qw + (n0 + brow) * K_DIM + bseg * 32;

    // MMA mapping: 8 warps as 4 (M) x 2 (N); warp tile 16m x 32n
    const int warp = tid >> 5, lane = tid & 31;
    const int wm = warp >> 1;               // 0..3
    const int wn = warp & 1;                // 0..1
    const int g4 = lane >> 2, tg = lane & 3;

    int acc[4][4];
#pragma unroll
    for (int i = 0; i < 4; i++)
#pragma unroll
        for (int j = 0; j < 4; j++) acc[i][j] = 0;

    int4 qr[8];   // raw qweight prefetch (32 ints = this thread's slice)
    int4 xr[2];   // packed-x prefetch (32 bytes)
    int  s2v, zv;

    // prefetch group 0
    {
#pragma unroll
        for (int j = 0; j < 8; j++) qr[j] = reinterpret_cast<const int4*>(qrowp)[j];
#pragma unroll
        for (int j = 0; j < 2; j++) {
            int u = tid + j * 256;
            int row = u >> 3, off = u & 7;
            xr[j] = reinterpret_cast<const int4*>(g_x_packed)[row * (K_DIM / 16) + off];
        }
        s2v = s2s[n0 + brow];
        zv  = s2z[n0 + brow];
    }

    for (int g = 0; g < G_DIM; ++g) {
        const int buf = g & 1;

        // ---- dequant + pack + store B tile (this thread: 32 weights) ----
        unsigned pk[8];
#pragma unroll
        for (int j = 0; j < 8; j++) {
            int w0 = qr[j].x * s2v + zv;
            int w1 = qr[j].y * s2v + zv;
            int w2 = qr[j].z * s2v + zv;
            int w3 = qr[j].w * s2v + zv;
            pk[j] = __byte_perm(__byte_perm((unsigned)w0, (unsigned)w1, 0x0040),
                                __byte_perm((unsigned)w2, (unsigned)w3, 0x0040), 0x5410);
        }
        {
            uint4* dst = reinterpret_cast<uint4*>(&sB[buf][brow * BROW + bseg * 32]);
            dst[0] = make_uint4(pk[0], pk[1], pk[2], pk[3]);
            dst[1] = make_uint4(pk[4], pk[5], pk[6], pk[7]);
        }
        // ---- store A tile ----
#pragma unroll
        for (int j = 0; j < 2; j++) {
            int u = tid + j * 256;
            int row = u >> 3, off = u & 7;
            *reinterpret_cast<int4*>(&sA[buf][row * BROW + off * 16]) = xr[j];
        }

        // ---- prefetch next group into registers (hidden under MMA) ----
        if (g + 1 < G_DIM) {
            const int* qp = qrowp + (g + 1) * GS;
#pragma unroll
            for (int j = 0; j < 8; j++) qr[j] = reinterpret_cast<const int4*>(qp)[j];
#pragma unroll
            for (int j = 0; j < 2; j++) {
                int u = tid + j * 256;
                int row = u >> 3, off = u & 7;
                xr[j] = reinterpret_cast<const int4*>(g_x_packed)
                            [row * (K_DIM / 16) + (g + 1) * (GS / 16) + off];
            }
            s2v = s2s[(g + 1) * N_DIM + n0 + brow];
            zv  = s2z[(g + 1) * N_DIM + n0 + brow];
        }

        __syncthreads();   // tile (buf) fully written; double buffering => 1 sync/iter

        // ---- MMA over this K-chunk: 4 k32 subtiles x 4 n8 subtiles ----
        const unsigned char* aBase = sA[buf];
        const unsigned char* bBase = sB[buf];
#pragma unroll
        for (int ks = 0; ks < 4; ks++) {
            unsigned a0 = *(const unsigned*)(aBase + (wm*16 + g4    ) * BROW + ks*32 + tg*4);
            unsigned a1 = *(const unsigned*)(aBase + (wm*16 + g4 + 8) * BROW + ks*32 + tg*4);
            unsigned a2 = *(const unsigned*)(aBase + (wm*16 + g4    ) * BROW + ks*32 + tg*4 + 16);
            unsigned a3 = *(const unsigned*)(aBase + (wm*16 + g4 + 8) * BROW + ks*32 + tg*4 + 16);
#pragma unroll
            for (int ns = 0; ns < 4; ns++) {
                const unsigned char* bp = bBase + (wn*32 + ns*8 + g4) * BROW + ks*32 + tg*4;
                unsigned b0 = *(const unsigned*)(bp);
                unsigned b1 = *(const unsigned*)(bp + 16);
                asm volatile(
                    "mma.sync.aligned.m16n8k32.row.col.s32.s8.s8.s32 "
                    "{%0,%1,%2,%3}, {%4,%5,%6,%7}, {%8,%9}, {%0,%1,%2,%3};\n"
                    : "+r"(acc[ns][0]), "+r"(acc[ns][1]),
                      "+r"(acc[ns][2]), "+r"(acc[ns][3])
                    : "r"(a0), "r"(a1), "r"(a2), "r"(a3), "r"(b0), "r"(b1));
            }
        }
    }

    // ---- epilogue: out = acc * isc[m] * s1[n] + bias[n] ----
    const int m0 = wm * 16 + g4;
    const float isc0 = isc[m0];
    const float isc1 = isc[m0 + 8];
#pragma unroll
    for (int ns = 0; ns < 4; ns++) {
        const int n = n0 + wn * 32 + ns * 8 + tg * 2;
        const float s1a = s1[n],   s1b = s1[n + 1];
        const float ba  = bias[n], bb  = bias[n + 1];
        out[ m0      * N_DIM + n    ] = (float)acc[ns][0] * isc0 * s1a + ba;
        out[ m0      * N_DIM + n + 1] = (float)acc[ns][1] * isc0 * s1b + bb;
        out[(m0 + 8) * N_DIM + n    ] = (float)acc[ns][2] * isc1 * s1a + ba;
        out[(m0 + 8) * N_DIM + n + 1] = (float)acc[ns][3] * isc1 * s1b + bb;
    }
}

// ---------------------------------------------------------------------------
extern "C" void kernel_launch(void* const* d_in, const int* in_sizes, int n_in,
                              void* d_out, int out_size) {
    const int*   x    = (const int*)  d_in[0];  // [M,K] int32 (int8 values)
    const float* isc  = (const float*)d_in[1];  // [M]
    // d_in[2] = input_sum (unused)
    const int*   qw   = (const int*)  d_in[3];  // [N,K] int32 (uint4 values)
    const int*   s2s  = (const int*)  d_in[4];  // [G,N]
    const int*   s2z  = (const int*)  d_in[5];  // [G,N]
    const float* s1   = (const float*)d_in[6];  // [N]
    const float* bias = (const float*)d_in[7];  // [N]
    float* out = (float*)d_out;

    pack_x_kernel<<<(M_DIM * K_DIM / 4 + 255) / 256, 256>>>(x);
    w4a8_gemm_kernel<<<N_DIM / NT, 256>>>(qw, s2s, s2z, isc, s1, bias, out);
}